// round 13
// baseline (speedup 1.0000x reference)
#include <cuda_runtime.h>
#include <cstdint>

#define NB 4913              // 17^3 triples
#define NH 2457              // packed u16 hist words (2 triples/word)
#define B_ 8
#define OHW 504
#define PLANE (OHW*OHW)      // 254016 (divisible by 64)
#define NPIX (B_*PLANE)      // 2032128
#define CH 32

__device__ unsigned short g_triple[NPIX];
__device__ unsigned int   g_hist[NB];             // zero-init; re-zeroed by k_expand
__device__ __align__(16)  float g_z1T[CH*NB];     // transposed: [o][t]
__device__ __align__(128) float g_lut[NB*CH];     // row-major: [t][o], 128B rows

// ---------------------------------------------------------------- packed 17-bin byte histogram
__device__ __forceinline__ void padd(unsigned h[5], unsigned b) {
    unsigned inc = 1u << ((b & 3u) * 8u);
    unsigned w = b >> 2;
    h[0] += (w == 0) ? inc : 0u;
    h[1] += (w == 1) ? inc : 0u;
    h[2] += (w == 2) ? inc : 0u;
    h[3] += (w == 3) ? inc : 0u;
    h[4] += (w == 4) ? inc : 0u;
}
__device__ __forceinline__ void psub(unsigned h[5], unsigned b) {
    unsigned inc = 1u << ((b & 3u) * 8u);
    unsigned w = b >> 2;
    h[0] -= (w == 0) ? inc : 0u;
    h[1] -= (w == 1) ? inc : 0u;
    h[2] -= (w == 2) ? inc : 0u;
    h[3] -= (w == 3) ? inc : 0u;
    h[4] -= (w == 4) ? inc : 0u;
}

// first-max argmax over 17 byte counters (ascending bins => lowest bin wins ties)
__device__ __forceinline__ int argmax17(const unsigned h[5]) {
    unsigned m = __vmaxu4(__vmaxu4(h[0], h[1]), __vmaxu4(h[2], h[3]));
    m = __vmaxu4(m, h[4]);
    m = __vmaxu4(m, m >> 16);
    m = __vmaxu4(m, m >> 8);
    unsigned M = (m & 0xFFu) * 0x01010101u;
    unsigned e;
    e = __vcmpeq4(h[0], M); if (e) return (int)((__ffs(e) - 1) >> 3);
    e = __vcmpeq4(h[1], M); if (e) return 4  + (int)((__ffs(e) - 1) >> 3);
    e = __vcmpeq4(h[2], M); if (e) return 8  + (int)((__ffs(e) - 1) >> 3);
    e = __vcmpeq4(h[3], M); if (e) return 12 + (int)((__ffs(e) - 1) >> 3);
    return 16;
}

// quantize one float to bin (round-half-even, matching jnp: (x*255)/16 then rint)
__device__ __forceinline__ int qbin(float v) {
    int r = __float2int_rn(__fmul_rn(v, 255.0f) * 0.0625f);
    return max(0, min(16, r));
}

#define TY 8
#define TX 118
#define TXP 128          // input columns per tile (halo-padded)
#define TXS 132          // swizzle-padded scol width

__device__ __forceinline__ int pxi(int x) { return x + (x >> 5); }   // bank-swizzle index

__global__ __launch_bounds__(256) void k_mode(const float* __restrict__ x) {
    __shared__ unsigned char  sbin[2][18][TXP];     // 4608 B (ping-pong)
    __shared__ unsigned int   scol[5][TY][TXS];     // 21120 B, swizzled x-index
    __shared__ unsigned int   shist[NH];            // 9828 B (u16-packed)

    int tid = threadIdx.x;
    int b   = blockIdx.z;
    int OY0 = blockIdx.y * TY;
    int OX0 = blockIdx.x * TX;
    int TXv = min(TX, OHW - OX0);                   // valid output cols this tile
    bool interior = (OY0 >= 1) && (OY0 + 17 <= 512) && (OX0 >= 1) && (OX0 + 127 <= 512);

    for (int i = tid; i < NH; i += 256) shist[i] = 0u;

    const float* base = x + (size_t)b * 3 * 512 * 512;

    int yy = tid >> 5;
    int lane = tid & 31;
    int x0 = lane * 4;
    unsigned tl[4] = {0, 0, 0, 0};                  // register triple accumulators

    // ---- load + quantize channel c into sbin[c&1] (padding / out-of-tile -> bin 0)
    auto load_plane = [&](int c) {
        const float* plane = base + (size_t)c * 512 * 512;
        unsigned char (*sb)[TXP] = sbin[c & 1];
        if (interior) {
            const float* p = plane + (size_t)(OY0 - 1) * 512 + (OX0 - 1);
            #pragma unroll
            for (int k = 0; k < 9; k++) {           // 9*256 == 18*128 exactly
                int i = tid + k * 256;
                int iy = i >> 7, jx = i & 127;
                sb[iy][jx] = (unsigned char)qbin(p[iy * 512 + jx]);
            }
        } else {
            #pragma unroll
            for (int k = 0; k < 9; k++) {
                int i = tid + k * 256;
                int iy = i >> 7, jx = i & 127;
                int gy = OY0 - 1 + iy, gx = OX0 - 1 + jx;
                float v = -1.0f;                    // qbin(-1) -> 0 (pad)
                if (gy >= 0 && gy < 512 && gx >= 0 && gx < 512) v = plane[gy * 512 + gx];
                sb[iy][jx] = (unsigned char)qbin(v);
            }
        }
    };

    load_plane(0);
    __syncthreads();

    for (int c = 0; c < 3; c++) {
        const unsigned char (*sb)[TXP] = sbin[c & 1];
        // ---- column histograms, y-sliding; init split into 2 independent chains (ILP)
        {
            int jx = tid & 127;
            int y0 = (tid >> 7) * 4;                 // 0 or 4
            int pj = pxi(jx);
            unsigned hA[5] = {0, 0, 0, 0, 0};
            unsigned hB[5] = {0, 0, 0, 0, 0};
            #pragma unroll
            for (int r = 0; r < 6; r++)  padd(hA, (unsigned)sb[y0 + r][jx]);
            #pragma unroll
            for (int r = 6; r < 11; r++) padd(hB, (unsigned)sb[y0 + r][jx]);
            unsigned h[5];
            #pragma unroll
            for (int w = 0; w < 5; w++) { h[w] = hA[w] + hB[w]; scol[w][y0][pj] = h[w]; }
            #pragma unroll
            for (int k = 1; k < 4; k++) {
                padd(h, (unsigned)sb[y0 + 10 + k][jx]);
                psub(h, (unsigned)sb[y0 + k - 1][jx]);
                #pragma unroll
                for (int w = 0; w < 5; w++) scol[w][y0 + k][pj] = h[w];
            }
        }
        // ---- issue next channel's loads into the OTHER sbin buffer
        if (c < 2) load_plane(c + 1);
        __syncthreads();   // orders scol for slide AND sbin[(c+1)&1] for next col
        // ---- sliding window in x, shuffle-assisted init:
        //      W(4l) = A(l) + A(l+1) + A(l+2) - C(4l+11),  A(l) = C(4l..4l+3)
        {
            unsigned A[5];
            #pragma unroll
            for (int w = 0; w < 5; w++) {
                A[w] = scol[w][yy][pxi(x0)]     + scol[w][yy][pxi(x0 + 1)]
                     + scol[w][yy][pxi(x0 + 2)] + scol[w][yy][pxi(x0 + 3)];
            }
            int xs = min(x0 + 11, TXP - 1);          // clamp for lanes 30/31 (unused)
            unsigned h[5];
            #pragma unroll
            for (int w = 0; w < 5; w++) {
                unsigned a1 = __shfl_down_sync(0xFFFFFFFFu, A[w], 1);
                unsigned a2 = __shfl_down_sync(0xFFFFFFFFu, A[w], 2);
                h[w] = A[w] + a1 + a2 - scol[w][yy][pxi(xs)];
            }
            if (x0 < TXv) {
                unsigned mul = (c == 0) ? 289u : (c == 1) ? 17u : 1u;
                int xe = min(x0 + 4, TXv);
                #pragma unroll
                for (int k = 0; k < 4; k++) {
                    int xx = x0 + k;
                    if (xx < xe) {
                        tl[k] += (unsigned)argmax17(h) * mul;
                        if (xx + 1 < xe) {
                            int pa = pxi(xx + 11), pb = pxi(xx);
                            #pragma unroll
                            for (int w = 0; w < 5; w++)
                                h[w] += scol[w][yy][pa] - scol[w][yy][pb];
                        }
                    }
                }
            }
        }
        __syncthreads();   // protects scol before next channel's column phase
    }
    // ---- write triples (packed u32 pairs, first pair always valid; tail guard on second)
    if (x0 < TXv) {
        int xe = min(x0 + 4, TXv);                   // 2 or 4 valid pixels (TXv even)
        size_t orow = ((size_t)b * OHW + OY0 + yy) * OHW + OX0 + x0;
        unsigned int* op = reinterpret_cast<unsigned int*>(&g_triple[orow]);
        op[0] = tl[0] | (tl[1] << 16);
        atomicAdd(&shist[tl[0] >> 1], 1u << ((tl[0] & 1u) * 16u));
        atomicAdd(&shist[tl[1] >> 1], 1u << ((tl[1] & 1u) * 16u));
        if (xe == x0 + 4) {
            op[1] = tl[2] | (tl[3] << 16);
            atomicAdd(&shist[tl[2] >> 1], 1u << ((tl[2] & 1u) * 16u));
            atomicAdd(&shist[tl[3] >> 1], 1u << ((tl[3] & 1u) * 16u));
        }
    }
    __syncthreads();
    for (int i = tid; i < NH; i += 256) {
        unsigned wv = shist[i];
        unsigned lo = wv & 0xFFFFu, hi = wv >> 16;
        if (lo) atomicAdd(&g_hist[2 * i], lo);
        if (hi) atomicAdd(&g_hist[2 * i + 1], hi);
    }
}

// ---------------------------------------------------------------- block reduce (2 doubles) + broadcast (512 threads)
__device__ __forceinline__ void reduce_bcast512(double& s, double& s2, float* mean, float* rstd) {
    int tid = threadIdx.x, lane = tid & 31, wid = tid >> 5;
    #pragma unroll
    for (int off = 16; off; off >>= 1) {
        s  += __shfl_down_sync(0xFFFFFFFFu, s,  off);
        s2 += __shfl_down_sync(0xFFFFFFFFu, s2, off);
    }
    __shared__ double sh[16][2];
    __shared__ float  bc[2];
    if (lane == 0) { sh[wid][0] = s; sh[wid][1] = s2; }
    __syncthreads();
    if (tid == 0) {
        double ts = 0.0, tq = 0.0;
        #pragma unroll
        for (int w = 0; w < 16; w++) { ts += sh[w][0]; tq += sh[w][1]; }
        double mn = ts / (double)NPIX;
        double vr = tq / (double)NPIX - mn * mn;
        if (vr < 0.0) vr = 0.0;
        bc[0] = (float)mn;
        bc[1] = (float)(1.0 / sqrt(vr + 1e-5));
    }
    __syncthreads();
    *mean = bc[0]; *rstd = bc[1];
}

// ---------------------------------------------------------------- fused stage-1: BN stats + z1 (512 threads)
__global__ __launch_bounds__(512) void kA(const float* __restrict__ w1, const float* __restrict__ b1,
                                          const float* __restrict__ wd1, const float* __restrict__ bd1,
                                          const float* __restrict__ g1, const float* __restrict__ be1) {
    int o = blockIdx.x, tid = threadIdx.x;
    float wa = w1[o * 3], wb = w1[o * 3 + 1], wc = w1[o * 3 + 2];
    float bb = b1[o], wdv = wd1[o], bdv = bd1[o];
    float gg = g1[o], bee = be1[o];
    float ys[10];
    double s = 0.0, s2 = 0.0;
    #pragma unroll
    for (int i = 0; i < 10; i++) {
        int t = tid + i * 512;
        if (t < NB) {
            int m0 = t / 289; int rem = t - m0 * 289; int m1 = rem / 17; int m2 = rem - m1 * 17;
            float y = (wa * (float)m0 + wb * (float)m1 + wc * (float)m2) * 0.0625f + bb;
            y = y * wdv + bdv;
            ys[i] = y;
            double n = (double)g_hist[t];
            s  += n * (double)y;
            s2 += n * (double)y * (double)y;
        }
    }
    float mean, rstd;
    reduce_bcast512(s, s2, &mean, &rstd);
    #pragma unroll
    for (int i = 0; i < 10; i++) {
        int t = tid + i * 512;
        if (t < NB) {
            float z = (ys[i] - mean) * rstd * gg + bee;
            z = (z >= 0.f) ? z : 0.01f * z;
            g_z1T[o * NB + t] = z;
        }
    }
}

// ---------------------------------------------------------------- fused stage-2: BN stats + final LUT (512 threads)
__global__ __launch_bounds__(512) void kB(const float* __restrict__ w2, const float* __restrict__ b2,
                                          const float* __restrict__ wd2, const float* __restrict__ bd2,
                                          const float* __restrict__ g2, const float* __restrict__ be2) {
    int o = blockIdx.x, tid = threadIdx.x;
    __shared__ float wsh[CH];
    if (tid < CH) wsh[tid] = w2[o * CH + tid];
    __syncthreads();
    float bb = b2[o], wdv = wd2[o], bdv = bd2[o];
    float gg = g2[o], bee = be2[o];
    float ys[10];
    double s = 0.0, s2 = 0.0;
    #pragma unroll
    for (int i = 0; i < 10; i++) {
        int t = tid + i * 512;
        if (t < NB) {
            float acc = 0.f;
            #pragma unroll
            for (int c = 0; c < CH; c++) acc += wsh[c] * g_z1T[c * NB + t];
            float y = (acc + bb) * wdv + bdv;
            ys[i] = y;
            double n = (double)g_hist[t];
            s  += n * (double)y;
            s2 += n * (double)y * (double)y;
        }
    }
    float mean, rstd;
    reduce_bcast512(s, s2, &mean, &rstd);
    #pragma unroll
    for (int i = 0; i < 10; i++) {
        int t = tid + i * 512;
        if (t < NB) {
            float z = (ys[i] - mean) * rstd * gg + bee;
            z = (z >= 0.f) ? z : 0.01f * z;
            g_lut[t * CH + o] = z;
        }
    }
}

// ---------------------------------------------------------------- expand to [8,32,504,504]
// Warp-cooperative gather + split software pipeline (triple 2 ahead, LUT 1 ahead),
// streaming stores. EXP_PASS=16 (1992 blocks) is the validated optimum.
#define EXP_PX 64            // pixels per pass (PLANE % 64 == 0)
#define EXP_PASS 16          // passes per block => 1024 px/block
__global__ __launch_bounds__(256) void k_expand(float* __restrict__ out) {
    __shared__ float sm[2][CH][66];   // 16896 B
    int tid  = threadIdx.x;
    int w    = tid >> 5, lane = tid & 31;
    int b    = blockIdx.y;
    int r0   = blockIdx.x * (EXP_PX * EXP_PASS);

    // re-zero g_hist for the next graph replay (k_expand never reads it)
    if (b == 0 && blockIdx.x < 20) {
        int i = blockIdx.x * 256 + tid;
        if (i < NB) g_hist[i] = 0u;
    }

    const unsigned short* trip = g_triple + (size_t)b * PLANE;
    float* ob = out + (size_t)b * CH * PLANE;

    int c  = lane & 3;            // float4 chunk within row
    int pl = w * 8 + (lane >> 2); // pixel-local 0..63
    int npass = min(EXP_PASS, (PLANE - r0) / EXP_PX);

    // prologue: gather pass 0, prefetch triple for pass 1
    unsigned t0 = (unsigned)trip[r0 + pl];
    const float4* row = reinterpret_cast<const float4*>(g_lut + (size_t)t0 * CH);
    float4 v0 = row[c];
    float4 v1 = row[c + 4];
    unsigned tn = (npass > 1) ? (unsigned)trip[r0 + EXP_PX + pl] : 0u;

    for (int pass = 0; pass < npass; pass++) {
        int p0  = r0 + pass * EXP_PX;
        int buf = pass & 1;
        int ch0 = 4 * c;
        sm[buf][ch0 + 0][pl]  = v0.x;
        sm[buf][ch0 + 1][pl]  = v0.y;
        sm[buf][ch0 + 2][pl]  = v0.z;
        sm[buf][ch0 + 3][pl]  = v0.w;
        sm[buf][ch0 + 16][pl] = v1.x;
        sm[buf][ch0 + 17][pl] = v1.y;
        sm[buf][ch0 + 18][pl] = v1.z;
        sm[buf][ch0 + 19][pl] = v1.w;
        if (pass + 1 < npass) {
            const float4* rn = reinterpret_cast<const float4*>(g_lut + (size_t)tn * CH);
            v0 = rn[c];
            v1 = rn[c + 4];
        }
        if (pass + 2 < npass) {
            tn = (unsigned)trip[p0 + 2 * EXP_PX + pl];
        }
        __syncthreads();
        #pragma unroll
        for (int k = 0; k < 4; k++) {
            int ch = w * 4 + k;
            float2 v = *reinterpret_cast<const float2*>(&sm[buf][ch][lane * 2]);
            __stcs(reinterpret_cast<float2*>(&ob[(size_t)ch * PLANE + p0 + lane * 2]), v);
        }
    }
}

// ---------------------------------------------------------------- launch
extern "C" void kernel_launch(void* const* d_in, const int* in_sizes, int n_in,
                              void* d_out, int out_size) {
    const float* x   = (const float*)d_in[0];
    const float* w1  = (const float*)d_in[1];
    const float* b1  = (const float*)d_in[2];
    const float* wd1 = (const float*)d_in[3];
    const float* bd1 = (const float*)d_in[4];
    const float* g1  = (const float*)d_in[5];
    const float* be1 = (const float*)d_in[6];
    const float* w2  = (const float*)d_in[7];
    const float* b2  = (const float*)d_in[8];
    const float* wd2 = (const float*)d_in[9];
    const float* bd2 = (const float*)d_in[10];
    const float* g2  = (const float*)d_in[11];
    const float* be2 = (const float*)d_in[12];
    float* out = (float*)d_out;

    k_mode<<<dim3((OHW + TX - 1) / TX, OHW / TY, B_), 256>>>(x);   // (5,63,8)
    kA<<<CH, 512>>>(w1, b1, wd1, bd1, g1, be1);
    kB<<<CH, 512>>>(w2, b2, wd2, bd2, g2, be2);
    int xblocks = (PLANE + EXP_PX * EXP_PASS - 1) / (EXP_PX * EXP_PASS);  // 249
    k_expand<<<dim3(xblocks, B_), 256>>>(out);
}

// round 14
// speedup vs baseline: 1.0236x; 1.0236x over previous
#include <cuda_runtime.h>
#include <cstdint>

#define NB 4913              // 17^3 triples
#define NH 2457              // packed u16 hist words (2 triples/word)
#define B_ 8
#define OHW 504
#define PLANE (OHW*OHW)      // 254016 (divisible by 64)
#define NPIX (B_*PLANE)      // 2032128
#define CH 32

__device__ unsigned short g_triple[NPIX];
__device__ unsigned int   g_hist[NB];             // zero-init; re-zeroed by k_expand
__device__ __align__(16)  float g_z1T[CH*NB];     // transposed: [o][t]
__device__ __align__(128) float g_lut[NB*CH];     // row-major: [t][o], 128B rows

// ---------------------------------------------------------------- packed 17-bin byte histogram
__device__ __forceinline__ void padd(unsigned h[5], unsigned b) {
    unsigned inc = 1u << ((b & 3u) * 8u);
    unsigned w = b >> 2;
    h[0] += (w == 0) ? inc : 0u;
    h[1] += (w == 1) ? inc : 0u;
    h[2] += (w == 2) ? inc : 0u;
    h[3] += (w == 3) ? inc : 0u;
    h[4] += (w == 4) ? inc : 0u;
}
__device__ __forceinline__ void psub(unsigned h[5], unsigned b) {
    unsigned inc = 1u << ((b & 3u) * 8u);
    unsigned w = b >> 2;
    h[0] -= (w == 0) ? inc : 0u;
    h[1] -= (w == 1) ? inc : 0u;
    h[2] -= (w == 2) ? inc : 0u;
    h[3] -= (w == 3) ? inc : 0u;
    h[4] -= (w == 4) ? inc : 0u;
}

// first-max argmax over 17 byte counters (ascending bins => lowest bin wins ties)
__device__ __forceinline__ int argmax17(const unsigned h[5]) {
    unsigned m = __vmaxu4(__vmaxu4(h[0], h[1]), __vmaxu4(h[2], h[3]));
    m = __vmaxu4(m, h[4]);
    m = __vmaxu4(m, m >> 16);
    m = __vmaxu4(m, m >> 8);
    unsigned M = (m & 0xFFu) * 0x01010101u;
    unsigned e;
    e = __vcmpeq4(h[0], M); if (e) return (int)((__ffs(e) - 1) >> 3);
    e = __vcmpeq4(h[1], M); if (e) return 4  + (int)((__ffs(e) - 1) >> 3);
    e = __vcmpeq4(h[2], M); if (e) return 8  + (int)((__ffs(e) - 1) >> 3);
    e = __vcmpeq4(h[3], M); if (e) return 12 + (int)((__ffs(e) - 1) >> 3);
    return 16;
}

// quantize one float to bin (round-half-even, matching jnp: (x*255)/16 then rint)
__device__ __forceinline__ int qbin(float v) {
    int r = __float2int_rn(__fmul_rn(v, 255.0f) * 0.0625f);
    return max(0, min(16, r));
}

#define TY 8
#define TX 118
#define TXP 128          // input columns per tile (halo-padded)
#define TXS 132          // swizzle-padded scol width

__device__ __forceinline__ int pxi(int x) { return x + (x >> 5); }   // bank-swizzle index

__global__ __launch_bounds__(256) void k_mode(const float* __restrict__ x) {
    __shared__ unsigned char  sbin[2][18][TXP];     // 4608 B (ping-pong)
    __shared__ unsigned int   scol[5][TY][TXS];     // 21120 B, swizzled x-index
    __shared__ unsigned int   shist[NH];            // 9828 B (u16-packed)

    int tid = threadIdx.x;
    int b   = blockIdx.z;
    int OY0 = blockIdx.y * TY;
    int OX0 = blockIdx.x * TX;
    int TXv = min(TX, OHW - OX0);                   // valid output cols this tile
    bool interior = (OY0 >= 1) && (OY0 + 17 <= 512) && (OX0 >= 1) && (OX0 + 127 <= 512);

    for (int i = tid; i < NH; i += 256) shist[i] = 0u;

    const float* base = x + (size_t)b * 3 * 512 * 512;

    int yy = tid >> 5;
    int lane = tid & 31;
    int x0 = lane * 4;
    unsigned tl[4] = {0, 0, 0, 0};                  // register triple accumulators

    // ---- load + quantize channel c into sbin[c&1] (padding / out-of-tile -> bin 0)
    auto load_plane = [&](int c) {
        const float* plane = base + (size_t)c * 512 * 512;
        unsigned char (*sb)[TXP] = sbin[c & 1];
        if (interior) {
            const float* p = plane + (size_t)(OY0 - 1) * 512 + (OX0 - 1);
            #pragma unroll
            for (int k = 0; k < 9; k++) {           // 9*256 == 18*128 exactly
                int i = tid + k * 256;
                int iy = i >> 7, jx = i & 127;
                sb[iy][jx] = (unsigned char)qbin(p[iy * 512 + jx]);
            }
        } else {
            #pragma unroll
            for (int k = 0; k < 9; k++) {
                int i = tid + k * 256;
                int iy = i >> 7, jx = i & 127;
                int gy = OY0 - 1 + iy, gx = OX0 - 1 + jx;
                float v = -1.0f;                    // qbin(-1) -> 0 (pad)
                if (gy >= 0 && gy < 512 && gx >= 0 && gx < 512) v = plane[gy * 512 + gx];
                sb[iy][jx] = (unsigned char)qbin(v);
            }
        }
    };

    load_plane(0);
    __syncthreads();

    for (int c = 0; c < 3; c++) {
        const unsigned char (*sb)[TXP] = sbin[c & 1];
        // ---- column histograms, y-sliding: 128 columns x 2 half-strips = 256 tasks
        {
            int jx = tid & 127;
            int y0 = (tid >> 7) * 4;                 // 0 or 4
            int pj = pxi(jx);
            unsigned h[5] = {0, 0, 0, 0, 0};
            #pragma unroll
            for (int r = 0; r < 11; r++) padd(h, (unsigned)sb[y0 + r][jx]);
            #pragma unroll
            for (int w = 0; w < 5; w++) scol[w][y0][pj] = h[w];
            #pragma unroll
            for (int k = 1; k < 4; k++) {
                padd(h, (unsigned)sb[y0 + 10 + k][jx]);
                psub(h, (unsigned)sb[y0 + k - 1][jx]);
                #pragma unroll
                for (int w = 0; w < 5; w++) scol[w][y0 + k][pj] = h[w];
            }
        }
        // ---- issue next channel's loads into the OTHER sbin buffer
        if (c < 2) load_plane(c + 1);
        __syncthreads();   // orders scol for slide AND sbin[(c+1)&1] for next col
        // ---- sliding window in x, shuffle-assisted init:
        //      W(4l) = A(l) + A(l+1) + A(l+2) - C(4l+11),  A(l) = C(4l..4l+3)
        {
            unsigned A[5];
            #pragma unroll
            for (int w = 0; w < 5; w++) {
                A[w] = scol[w][yy][pxi(x0)]     + scol[w][yy][pxi(x0 + 1)]
                     + scol[w][yy][pxi(x0 + 2)] + scol[w][yy][pxi(x0 + 3)];
            }
            int xs = min(x0 + 11, TXP - 1);          // clamp for lanes 30/31 (unused)
            unsigned h[5];
            #pragma unroll
            for (int w = 0; w < 5; w++) {
                unsigned a1 = __shfl_down_sync(0xFFFFFFFFu, A[w], 1);
                unsigned a2 = __shfl_down_sync(0xFFFFFFFFu, A[w], 2);
                h[w] = A[w] + a1 + a2 - scol[w][yy][pxi(xs)];
            }
            if (x0 < TXv) {
                unsigned mul = (c == 0) ? 289u : (c == 1) ? 17u : 1u;
                int xe = min(x0 + 4, TXv);
                #pragma unroll
                for (int k = 0; k < 4; k++) {
                    int xx = x0 + k;
                    if (xx < xe) {
                        tl[k] += (unsigned)argmax17(h) * mul;
                        if (xx + 1 < xe) {
                            int pa = pxi(xx + 11), pb = pxi(xx);
                            #pragma unroll
                            for (int w = 0; w < 5; w++)
                                h[w] += scol[w][yy][pa] - scol[w][yy][pb];
                        }
                    }
                }
            }
        }
        __syncthreads();   // protects scol before next channel's column phase
    }
    // ---- write triples (packed u32 pairs, first pair always valid; tail guard on second)
    if (x0 < TXv) {
        int xe = min(x0 + 4, TXv);                   // 2 or 4 valid pixels (TXv even)
        size_t orow = ((size_t)b * OHW + OY0 + yy) * OHW + OX0 + x0;
        unsigned int* op = reinterpret_cast<unsigned int*>(&g_triple[orow]);
        op[0] = tl[0] | (tl[1] << 16);
        atomicAdd(&shist[tl[0] >> 1], 1u << ((tl[0] & 1u) * 16u));
        atomicAdd(&shist[tl[1] >> 1], 1u << ((tl[1] & 1u) * 16u));
        if (xe == x0 + 4) {
            op[1] = tl[2] | (tl[3] << 16);
            atomicAdd(&shist[tl[2] >> 1], 1u << ((tl[2] & 1u) * 16u));
            atomicAdd(&shist[tl[3] >> 1], 1u << ((tl[3] & 1u) * 16u));
        }
    }
    __syncthreads();
    for (int i = tid; i < NH; i += 256) {
        unsigned wv = shist[i];
        unsigned lo = wv & 0xFFFFu, hi = wv >> 16;
        if (lo) atomicAdd(&g_hist[2 * i], lo);
        if (hi) atomicAdd(&g_hist[2 * i + 1], hi);
    }
}

// ---------------------------------------------------------------- block reduce (2 doubles) + broadcast
__device__ __forceinline__ void reduce_bcast(double& s, double& s2, float* mean, float* rstd) {
    int tid = threadIdx.x, lane = tid & 31, wid = tid >> 5;
    #pragma unroll
    for (int off = 16; off; off >>= 1) {
        s  += __shfl_down_sync(0xFFFFFFFFu, s,  off);
        s2 += __shfl_down_sync(0xFFFFFFFFu, s2, off);
    }
    __shared__ double sh[8][2];
    __shared__ float  bc[2];
    if (lane == 0) { sh[wid][0] = s; sh[wid][1] = s2; }
    __syncthreads();
    if (tid == 0) {
        double ts = 0.0, tq = 0.0;
        #pragma unroll
        for (int w = 0; w < 8; w++) { ts += sh[w][0]; tq += sh[w][1]; }
        double mn = ts / (double)NPIX;
        double vr = tq / (double)NPIX - mn * mn;
        if (vr < 0.0) vr = 0.0;
        bc[0] = (float)mn;
        bc[1] = (float)(1.0 / sqrt(vr + 1e-5));
    }
    __syncthreads();
    *mean = bc[0]; *rstd = bc[1];
}

// ---------------------------------------------------------------- fused stage-1: BN stats + z1
// (256 threads; split accumulators halve the serial DFMA dependency chain)
__global__ __launch_bounds__(256) void kA(const float* __restrict__ w1, const float* __restrict__ b1,
                                          const float* __restrict__ wd1, const float* __restrict__ bd1,
                                          const float* __restrict__ g1, const float* __restrict__ be1) {
    int o = blockIdx.x, tid = threadIdx.x;
    float wa = w1[o * 3], wb = w1[o * 3 + 1], wc = w1[o * 3 + 2];
    float bb = b1[o], wdv = wd1[o], bdv = bd1[o];
    float gg = g1[o], bee = be1[o];
    float ys[20];
    double s0 = 0.0, s1 = 0.0, q0 = 0.0, q1 = 0.0;
    #pragma unroll
    for (int i = 0; i < 20; i++) {
        int t = tid + i * 256;
        if (t < NB) {
            int m0 = t / 289; int rem = t - m0 * 289; int m1 = rem / 17; int m2 = rem - m1 * 17;
            float y = (wa * (float)m0 + wb * (float)m1 + wc * (float)m2) * 0.0625f + bb;
            y = y * wdv + bdv;
            ys[i] = y;
            double n = (double)g_hist[t];
            double yd = (double)y;
            if (i & 1) { s1 += n * yd; q1 += n * yd * yd; }
            else       { s0 += n * yd; q0 += n * yd * yd; }
        }
    }
    double s = s0 + s1, s2 = q0 + q1;
    float mean, rstd;
    reduce_bcast(s, s2, &mean, &rstd);
    #pragma unroll
    for (int i = 0; i < 20; i++) {
        int t = tid + i * 256;
        if (t < NB) {
            float z = (ys[i] - mean) * rstd * gg + bee;
            z = (z >= 0.f) ? z : 0.01f * z;
            g_z1T[o * NB + t] = z;
        }
    }
}

// ---------------------------------------------------------------- fused stage-2: BN stats + final LUT
__global__ __launch_bounds__(256) void kB(const float* __restrict__ w2, const float* __restrict__ b2,
                                          const float* __restrict__ wd2, const float* __restrict__ bd2,
                                          const float* __restrict__ g2, const float* __restrict__ be2) {
    int o = blockIdx.x, tid = threadIdx.x;
    __shared__ float wsh[CH];
    if (tid < CH) wsh[tid] = w2[o * CH + tid];
    __syncthreads();
    float bb = b2[o], wdv = wd2[o], bdv = bd2[o];
    float gg = g2[o], bee = be2[o];
    float ys[20];
    double s0 = 0.0, s1 = 0.0, q0 = 0.0, q1 = 0.0;
    #pragma unroll
    for (int i = 0; i < 20; i++) {
        int t = tid + i * 256;
        if (t < NB) {
            float acc = 0.f;
            #pragma unroll
            for (int c = 0; c < CH; c++) acc += wsh[c] * g_z1T[c * NB + t];
            float y = (acc + bb) * wdv + bdv;
            ys[i] = y;
            double n = (double)g_hist[t];
            double yd = (double)y;
            if (i & 1) { s1 += n * yd; q1 += n * yd * yd; }
            else       { s0 += n * yd; q0 += n * yd * yd; }
        }
    }
    double s = s0 + s1, s2 = q0 + q1;
    float mean, rstd;
    reduce_bcast(s, s2, &mean, &rstd);
    #pragma unroll
    for (int i = 0; i < 20; i++) {
        int t = tid + i * 256;
        if (t < NB) {
            float z = (ys[i] - mean) * rstd * gg + bee;
            z = (z >= 0.f) ? z : 0.01f * z;
            g_lut[t * CH + o] = z;
        }
    }
}

// ---------------------------------------------------------------- expand to [8,32,504,504]
// Warp-cooperative gather + split software pipeline (triple 2 ahead, LUT 1 ahead),
// streaming stores. EXP_PASS=16 (1992 blocks) is the validated optimum.
#define EXP_PX 64            // pixels per pass (PLANE % 64 == 0)
#define EXP_PASS 16          // passes per block => 1024 px/block
__global__ __launch_bounds__(256) void k_expand(float* __restrict__ out) {
    __shared__ float sm[2][CH][66];   // 16896 B
    int tid  = threadIdx.x;
    int w    = tid >> 5, lane = tid & 31;
    int b    = blockIdx.y;
    int r0   = blockIdx.x * (EXP_PX * EXP_PASS);

    // re-zero g_hist for the next graph replay (k_expand never reads it)
    if (b == 0 && blockIdx.x < 20) {
        int i = blockIdx.x * 256 + tid;
        if (i < NB) g_hist[i] = 0u;
    }

    const unsigned short* trip = g_triple + (size_t)b * PLANE;
    float* ob = out + (size_t)b * CH * PLANE;

    int c  = lane & 3;            // float4 chunk within row
    int pl = w * 8 + (lane >> 2); // pixel-local 0..63
    int npass = min(EXP_PASS, (PLANE - r0) / EXP_PX);

    // prologue: gather pass 0, prefetch triple for pass 1
    unsigned t0 = (unsigned)trip[r0 + pl];
    const float4* row = reinterpret_cast<const float4*>(g_lut + (size_t)t0 * CH);
    float4 v0 = row[c];
    float4 v1 = row[c + 4];
    unsigned tn = (npass > 1) ? (unsigned)trip[r0 + EXP_PX + pl] : 0u;

    for (int pass = 0; pass < npass; pass++) {
        int p0  = r0 + pass * EXP_PX;
        int buf = pass & 1;
        int ch0 = 4 * c;
        sm[buf][ch0 + 0][pl]  = v0.x;
        sm[buf][ch0 + 1][pl]  = v0.y;
        sm[buf][ch0 + 2][pl]  = v0.z;
        sm[buf][ch0 + 3][pl]  = v0.w;
        sm[buf][ch0 + 16][pl] = v1.x;
        sm[buf][ch0 + 17][pl] = v1.y;
        sm[buf][ch0 + 18][pl] = v1.z;
        sm[buf][ch0 + 19][pl] = v1.w;
        if (pass + 1 < npass) {
            const float4* rn = reinterpret_cast<const float4*>(g_lut + (size_t)tn * CH);
            v0 = rn[c];
            v1 = rn[c + 4];
        }
        if (pass + 2 < npass) {
            tn = (unsigned)trip[p0 + 2 * EXP_PX + pl];
        }
        __syncthreads();
        #pragma unroll
        for (int k = 0; k < 4; k++) {
            int ch = w * 4 + k;
            float2 v = *reinterpret_cast<const float2*>(&sm[buf][ch][lane * 2]);
            __stcs(reinterpret_cast<float2*>(&ob[(size_t)ch * PLANE + p0 + lane * 2]), v);
        }
    }
}

// ---------------------------------------------------------------- launch
extern "C" void kernel_launch(void* const* d_in, const int* in_sizes, int n_in,
                              void* d_out, int out_size) {
    const float* x   = (const float*)d_in[0];
    const float* w1  = (const float*)d_in[1];
    const float* b1  = (const float*)d_in[2];
    const float* wd1 = (const float*)d_in[3];
    const float* bd1 = (const float*)d_in[4];
    const float* g1  = (const float*)d_in[5];
    const float* be1 = (const float*)d_in[6];
    const float* w2  = (const float*)d_in[7];
    const float* b2  = (const float*)d_in[8];
    const float* wd2 = (const float*)d_in[9];
    const float* bd2 = (const float*)d_in[10];
    const float* g2  = (const float*)d_in[11];
    const float* be2 = (const float*)d_in[12];
    float* out = (float*)d_out;

    k_mode<<<dim3((OHW + TX - 1) / TX, OHW / TY, B_), 256>>>(x);   // (5,63,8)
    kA<<<CH, 256>>>(w1, b1, wd1, bd1, g1, be1);
    kB<<<CH, 256>>>(w2, b2, wd2, bd2, g2, be2);
    int xblocks = (PLANE + EXP_PX * EXP_PASS - 1) / (EXP_PX * EXP_PASS);  // 249
    k_expand<<<dim3(xblocks, B_), 256>>>(out);
}

// round 15
// speedup vs baseline: 1.0605x; 1.0361x over previous
#include <cuda_runtime.h>
#include <cstdint>

#define NB 4913              // 17^3 triples
#define NH 2457              // packed u16 hist words (2 triples/word)
#define B_ 8
#define OHW 504
#define PLANE (OHW*OHW)      // 254016 (divisible by 64)
#define NPIX (B_*PLANE)      // 2032128
#define CH 32

__device__ unsigned short g_triple[NPIX];
__device__ unsigned int   g_hist[NB];             // zero-init; re-zeroed by k_expand
__device__ __align__(16)  float g_z1T[CH*NB];     // transposed: [o][t]
__device__ __align__(128) float g_lut[NB*CH];     // row-major: [t][o], 128B rows

// ---------------------------------------------------------------- packed 17-bin byte histogram
__device__ __forceinline__ void padd(unsigned h[5], unsigned b) {
    unsigned inc = 1u << ((b & 3u) * 8u);
    unsigned w = b >> 2;
    h[0] += (w == 0) ? inc : 0u;
    h[1] += (w == 1) ? inc : 0u;
    h[2] += (w == 2) ? inc : 0u;
    h[3] += (w == 3) ? inc : 0u;
    h[4] += (w == 4) ? inc : 0u;
}
__device__ __forceinline__ void psub(unsigned h[5], unsigned b) {
    unsigned inc = 1u << ((b & 3u) * 8u);
    unsigned w = b >> 2;
    h[0] -= (w == 0) ? inc : 0u;
    h[1] -= (w == 1) ? inc : 0u;
    h[2] -= (w == 2) ? inc : 0u;
    h[3] -= (w == 3) ? inc : 0u;
    h[4] -= (w == 4) ? inc : 0u;
}

// first-max argmax over 17 byte counters (ascending bins => lowest bin wins ties)
__device__ __forceinline__ int argmax17(const unsigned h[5]) {
    unsigned m = __vmaxu4(__vmaxu4(h[0], h[1]), __vmaxu4(h[2], h[3]));
    m = __vmaxu4(m, h[4]);
    m = __vmaxu4(m, m >> 16);
    m = __vmaxu4(m, m >> 8);
    unsigned M = (m & 0xFFu) * 0x01010101u;
    unsigned e;
    e = __vcmpeq4(h[0], M); if (e) return (int)((__ffs(e) - 1) >> 3);
    e = __vcmpeq4(h[1], M); if (e) return 4  + (int)((__ffs(e) - 1) >> 3);
    e = __vcmpeq4(h[2], M); if (e) return 8  + (int)((__ffs(e) - 1) >> 3);
    e = __vcmpeq4(h[3], M); if (e) return 12 + (int)((__ffs(e) - 1) >> 3);
    return 16;
}

// quantize one float to bin (round-half-even, matching jnp: (x*255)/16 then rint)
__device__ __forceinline__ int qbin(float v) {
    int r = __float2int_rn(__fmul_rn(v, 255.0f) * 0.0625f);
    return max(0, min(16, r));
}

#define TY 8
#define TX 118
#define TXP 128          // input columns per tile (halo-padded)
#define TXS 132          // swizzle-padded scol width

__device__ __forceinline__ int pxi(int x) { return x + (x >> 5); }   // bank-swizzle index

__global__ __launch_bounds__(256) void k_mode(const float* __restrict__ x) {
    __shared__ unsigned char  sbin[2][18][TXP];     // 4608 B (ping-pong)
    __shared__ unsigned int   scol[5][TY][TXS];     // 21120 B, swizzled x-index
    __shared__ unsigned int   shist[NH];            // 9828 B (u16-packed)

    int tid = threadIdx.x;
    int b   = blockIdx.z;
    int OY0 = blockIdx.y * TY;
    int OX0 = blockIdx.x * TX;
    int TXv = min(TX, OHW - OX0);                   // valid output cols this tile
    bool interior = (OY0 >= 1) && (OY0 + 17 <= 512) && (OX0 >= 1) && (OX0 + 127 <= 512);

    for (int i = tid; i < NH; i += 256) shist[i] = 0u;

    const float* base = x + (size_t)b * 3 * 512 * 512;

    int yy = tid >> 5;
    int lane = tid & 31;
    int x0 = lane * 4;
    unsigned tl[4] = {0, 0, 0, 0};                  // register triple accumulators

    // ---- load + quantize channel c into sbin[c&1] (padding / out-of-tile -> bin 0)
    auto load_plane = [&](int c) {
        const float* plane = base + (size_t)c * 512 * 512;
        unsigned char (*sb)[TXP] = sbin[c & 1];
        if (interior) {
            const float* p = plane + (size_t)(OY0 - 1) * 512 + (OX0 - 1);
            #pragma unroll
            for (int k = 0; k < 9; k++) {           // 9*256 == 18*128 exactly
                int i = tid + k * 256;
                int iy = i >> 7, jx = i & 127;
                sb[iy][jx] = (unsigned char)qbin(p[iy * 512 + jx]);
            }
        } else {
            #pragma unroll
            for (int k = 0; k < 9; k++) {
                int i = tid + k * 256;
                int iy = i >> 7, jx = i & 127;
                int gy = OY0 - 1 + iy, gx = OX0 - 1 + jx;
                float v = -1.0f;                    // qbin(-1) -> 0 (pad)
                if (gy >= 0 && gy < 512 && gx >= 0 && gx < 512) v = plane[gy * 512 + gx];
                sb[iy][jx] = (unsigned char)qbin(v);
            }
        }
    };

    load_plane(0);
    __syncthreads();

    for (int c = 0; c < 3; c++) {
        const unsigned char (*sb)[TXP] = sbin[c & 1];
        // ---- column histograms, y-sliding: 128 columns x 2 half-strips = 256 tasks
        {
            int jx = tid & 127;
            int y0 = (tid >> 7) * 4;                 // 0 or 4
            int pj = pxi(jx);
            unsigned h[5] = {0, 0, 0, 0, 0};
            #pragma unroll
            for (int r = 0; r < 11; r++) padd(h, (unsigned)sb[y0 + r][jx]);
            #pragma unroll
            for (int w = 0; w < 5; w++) scol[w][y0][pj] = h[w];
            #pragma unroll
            for (int k = 1; k < 4; k++) {
                padd(h, (unsigned)sb[y0 + 10 + k][jx]);
                psub(h, (unsigned)sb[y0 + k - 1][jx]);
                #pragma unroll
                for (int w = 0; w < 5; w++) scol[w][y0 + k][pj] = h[w];
            }
        }
        // ---- issue next channel's loads into the OTHER sbin buffer
        if (c < 2) load_plane(c + 1);
        __syncthreads();   // orders scol for slide AND sbin[(c+1)&1] for next col
        // ---- sliding window in x, shuffle-assisted init:
        //      W(4l) = A(l) + A(l+1) + A(l+2) - C(4l+11),  A(l) = C(4l..4l+3)
        {
            unsigned A[5];
            #pragma unroll
            for (int w = 0; w < 5; w++) {
                A[w] = scol[w][yy][pxi(x0)]     + scol[w][yy][pxi(x0 + 1)]
                     + scol[w][yy][pxi(x0 + 2)] + scol[w][yy][pxi(x0 + 3)];
            }
            int xs = min(x0 + 11, TXP - 1);          // clamp for lanes 30/31 (unused)
            unsigned h[5];
            #pragma unroll
            for (int w = 0; w < 5; w++) {
                unsigned a1 = __shfl_down_sync(0xFFFFFFFFu, A[w], 1);
                unsigned a2 = __shfl_down_sync(0xFFFFFFFFu, A[w], 2);
                h[w] = A[w] + a1 + a2 - scol[w][yy][pxi(xs)];
            }
            if (x0 < TXv) {
                unsigned mul = (c == 0) ? 289u : (c == 1) ? 17u : 1u;
                int xe = min(x0 + 4, TXv);
                #pragma unroll
                for (int k = 0; k < 4; k++) {
                    int xx = x0 + k;
                    if (xx < xe) {
                        tl[k] += (unsigned)argmax17(h) * mul;
                        if (xx + 1 < xe) {
                            int pa = pxi(xx + 11), pb = pxi(xx);
                            #pragma unroll
                            for (int w = 0; w < 5; w++)
                                h[w] += scol[w][yy][pa] - scol[w][yy][pb];
                        }
                    }
                }
            }
        }
        __syncthreads();   // protects scol before next channel's column phase
    }
    // ---- write triples (packed u32 pairs, first pair always valid; tail guard on second)
    if (x0 < TXv) {
        int xe = min(x0 + 4, TXv);                   // 2 or 4 valid pixels (TXv even)
        size_t orow = ((size_t)b * OHW + OY0 + yy) * OHW + OX0 + x0;
        unsigned int* op = reinterpret_cast<unsigned int*>(&g_triple[orow]);
        op[0] = tl[0] | (tl[1] << 16);
        atomicAdd(&shist[tl[0] >> 1], 1u << ((tl[0] & 1u) * 16u));
        atomicAdd(&shist[tl[1] >> 1], 1u << ((tl[1] & 1u) * 16u));
        if (xe == x0 + 4) {
            op[1] = tl[2] | (tl[3] << 16);
            atomicAdd(&shist[tl[2] >> 1], 1u << ((tl[2] & 1u) * 16u));
            atomicAdd(&shist[tl[3] >> 1], 1u << ((tl[3] & 1u) * 16u));
        }
    }
    __syncthreads();
    for (int i = tid; i < NH; i += 256) {
        unsigned wv = shist[i];
        unsigned lo = wv & 0xFFFFu, hi = wv >> 16;
        if (lo) atomicAdd(&g_hist[2 * i], lo);
        if (hi) atomicAdd(&g_hist[2 * i + 1], hi);
    }
}

// ---------------------------------------------------------------- block reduce (2 doubles) + broadcast
__device__ __forceinline__ void reduce_bcast(double& s, double& s2, float* mean, float* rstd) {
    int tid = threadIdx.x, lane = tid & 31, wid = tid >> 5;
    #pragma unroll
    for (int off = 16; off; off >>= 1) {
        s  += __shfl_down_sync(0xFFFFFFFFu, s,  off);
        s2 += __shfl_down_sync(0xFFFFFFFFu, s2, off);
    }
    __shared__ double sh[8][2];
    __shared__ float  bc[2];
    if (lane == 0) { sh[wid][0] = s; sh[wid][1] = s2; }
    __syncthreads();
    if (tid == 0) {
        double ts = 0.0, tq = 0.0;
        #pragma unroll
        for (int w = 0; w < 8; w++) { ts += sh[w][0]; tq += sh[w][1]; }
        double mn = ts / (double)NPIX;
        double vr = tq / (double)NPIX - mn * mn;
        if (vr < 0.0) vr = 0.0;
        bc[0] = (float)mn;
        bc[1] = (float)(1.0 / sqrt(vr + 1e-5));
    }
    __syncthreads();
    *mean = bc[0]; *rstd = bc[1];
}

// ---------------------------------------------------------------- fused stage-1: BN stats + z1
__global__ __launch_bounds__(256) void kA(const float* __restrict__ w1, const float* __restrict__ b1,
                                          const float* __restrict__ wd1, const float* __restrict__ bd1,
                                          const float* __restrict__ g1, const float* __restrict__ be1) {
    int o = blockIdx.x, tid = threadIdx.x;
    float wa = w1[o * 3], wb = w1[o * 3 + 1], wc = w1[o * 3 + 2];
    float bb = b1[o], wdv = wd1[o], bdv = bd1[o];
    float gg = g1[o], bee = be1[o];
    float ys[20];
    double s = 0.0, s2 = 0.0;
    #pragma unroll
    for (int i = 0; i < 20; i++) {
        int t = tid + i * 256;
        if (t < NB) {
            int m0 = t / 289; int rem = t - m0 * 289; int m1 = rem / 17; int m2 = rem - m1 * 17;
            float y = (wa * (float)m0 + wb * (float)m1 + wc * (float)m2) * 0.0625f + bb;
            y = y * wdv + bdv;
            ys[i] = y;
            double n = (double)g_hist[t];
            s  += n * (double)y;
            s2 += n * (double)y * (double)y;
        }
    }
    float mean, rstd;
    reduce_bcast(s, s2, &mean, &rstd);
    #pragma unroll
    for (int i = 0; i < 20; i++) {
        int t = tid + i * 256;
        if (t < NB) {
            float z = (ys[i] - mean) * rstd * gg + bee;
            z = (z >= 0.f) ? z : 0.01f * z;
            g_z1T[o * NB + t] = z;
        }
    }
}

// ---------------------------------------------------------------- fused stage-2: BN stats + final LUT
__global__ __launch_bounds__(256) void kB(const float* __restrict__ w2, const float* __restrict__ b2,
                                          const float* __restrict__ wd2, const float* __restrict__ bd2,
                                          const float* __restrict__ g2, const float* __restrict__ be2) {
    int o = blockIdx.x, tid = threadIdx.x;
    __shared__ float wsh[CH];
    if (tid < CH) wsh[tid] = w2[o * CH + tid];
    __syncthreads();
    float bb = b2[o], wdv = wd2[o], bdv = bd2[o];
    float gg = g2[o], bee = be2[o];
    float ys[20];
    double s = 0.0, s2 = 0.0;
    #pragma unroll
    for (int i = 0; i < 20; i++) {
        int t = tid + i * 256;
        if (t < NB) {
            float acc = 0.f;
            #pragma unroll
            for (int c = 0; c < CH; c++) acc += wsh[c] * g_z1T[c * NB + t];
            float y = (acc + bb) * wdv + bdv;
            ys[i] = y;
            double n = (double)g_hist[t];
            s  += n * (double)y;
            s2 += n * (double)y * (double)y;
        }
    }
    float mean, rstd;
    reduce_bcast(s, s2, &mean, &rstd);
    #pragma unroll
    for (int i = 0; i < 20; i++) {
        int t = tid + i * 256;
        if (t < NB) {
            float z = (ys[i] - mean) * rstd * gg + bee;
            z = (z >= 0.f) ? z : 0.01f * z;
            g_lut[t * CH + o] = z;
        }
    }
}

// ---------------------------------------------------------------- expand to [8,32,504,504]
// Warp-cooperative gather + split software pipeline (triple 2 ahead, LUT 1 ahead),
// streaming stores. EXP_PASS=16 (1992 blocks) is the validated optimum.
#define EXP_PX 64            // pixels per pass (PLANE % 64 == 0)
#define EXP_PASS 16          // passes per block => 1024 px/block
__global__ __launch_bounds__(256) void k_expand(float* __restrict__ out) {
    __shared__ float sm[2][CH][66];   // 16896 B
    int tid  = threadIdx.x;
    int w    = tid >> 5, lane = tid & 31;
    int b    = blockIdx.y;
    int r0   = blockIdx.x * (EXP_PX * EXP_PASS);

    // re-zero g_hist for the next graph replay (k_expand never reads it)
    if (b == 0 && blockIdx.x < 20) {
        int i = blockIdx.x * 256 + tid;
        if (i < NB) g_hist[i] = 0u;
    }

    const unsigned short* trip = g_triple + (size_t)b * PLANE;
    float* ob = out + (size_t)b * CH * PLANE;

    int c  = lane & 3;            // float4 chunk within row
    int pl = w * 8 + (lane >> 2); // pixel-local 0..63
    int npass = min(EXP_PASS, (PLANE - r0) / EXP_PX);

    // prologue: gather pass 0, prefetch triple for pass 1
    unsigned t0 = (unsigned)trip[r0 + pl];
    const float4* row = reinterpret_cast<const float4*>(g_lut + (size_t)t0 * CH);
    float4 v0 = row[c];
    float4 v1 = row[c + 4];
    unsigned tn = (npass > 1) ? (unsigned)trip[r0 + EXP_PX + pl] : 0u;

    for (int pass = 0; pass < npass; pass++) {
        int p0  = r0 + pass * EXP_PX;
        int buf = pass & 1;
        int ch0 = 4 * c;
        sm[buf][ch0 + 0][pl]  = v0.x;
        sm[buf][ch0 + 1][pl]  = v0.y;
        sm[buf][ch0 + 2][pl]  = v0.z;
        sm[buf][ch0 + 3][pl]  = v0.w;
        sm[buf][ch0 + 16][pl] = v1.x;
        sm[buf][ch0 + 17][pl] = v1.y;
        sm[buf][ch0 + 18][pl] = v1.z;
        sm[buf][ch0 + 19][pl] = v1.w;
        if (pass + 1 < npass) {
            const float4* rn = reinterpret_cast<const float4*>(g_lut + (size_t)tn * CH);
            v0 = rn[c];
            v1 = rn[c + 4];
        }
        if (pass + 2 < npass) {
            tn = (unsigned)trip[p0 + 2 * EXP_PX + pl];
        }
        __syncthreads();
        #pragma unroll
        for (int k = 0; k < 4; k++) {
            int ch = w * 4 + k;
            float2 v = *reinterpret_cast<const float2*>(&sm[buf][ch][lane * 2]);
            __stcs(reinterpret_cast<float2*>(&ob[(size_t)ch * PLANE + p0 + lane * 2]), v);
        }
    }
}

// ---------------------------------------------------------------- launch
extern "C" void kernel_launch(void* const* d_in, const int* in_sizes, int n_in,
                              void* d_out, int out_size) {
    const float* x   = (const float*)d_in[0];
    const float* w1  = (const float*)d_in[1];
    const float* b1  = (const float*)d_in[2];
    const float* wd1 = (const float*)d_in[3];
    const float* bd1 = (const float*)d_in[4];
    const float* g1  = (const float*)d_in[5];
    const float* be1 = (const float*)d_in[6];
    const float* w2  = (const float*)d_in[7];
    const float* b2  = (const float*)d_in[8];
    const float* wd2 = (const float*)d_in[9];
    const float* bd2 = (const float*)d_in[10];
    const float* g2  = (const float*)d_in[11];
    const float* be2 = (const float*)d_in[12];
    float* out = (float*)d_out;

    k_mode<<<dim3((OHW + TX - 1) / TX, OHW / TY, B_), 256>>>(x);   // (5,63,8)
    kA<<<CH, 256>>>(w1, b1, wd1, bd1, g1, be1);
    kB<<<CH, 256>>>(w2, b2, wd2, bd2, g2, be2);
    int xblocks = (PLANE + EXP_PX * EXP_PASS - 1) / (EXP_PX * EXP_PASS);  // 249
    k_expand<<<dim3(xblocks, B_), 256>>>(out);
}

// round 17
// speedup vs baseline: 1.0872x; 1.0251x over previous
#include <cuda_runtime.h>
#include <cstdint>

#define NB 4913              // 17^3 triples
#define NH 2457              // packed u16 hist words (2 triples/word)
#define B_ 8
#define OHW 504
#define PLANE (OHW*OHW)      // 254016 (divisible by 64)
#define NPIX (B_*PLANE)      // 2032128
#define CH 32

__device__ unsigned short g_triple[NPIX];
__device__ unsigned int   g_hist[NB];             // zero-init; re-zeroed by k_expand
__device__ __align__(16)  float g_z1T[CH*NB];     // transposed: [o][t]
__device__ __align__(128) float g_lut[NB*CH];     // row-major: [t][o], 128B rows

// ---------------------------------------------------------------- packed 17-bin byte histogram
__device__ __forceinline__ void padd(unsigned h[5], unsigned b) {
    unsigned inc = 1u << ((b & 3u) * 8u);
    unsigned w = b >> 2;
    h[0] += (w == 0) ? inc : 0u;
    h[1] += (w == 1) ? inc : 0u;
    h[2] += (w == 2) ? inc : 0u;
    h[3] += (w == 3) ? inc : 0u;
    h[4] += (w == 4) ? inc : 0u;
}
__device__ __forceinline__ void psub(unsigned h[5], unsigned b) {
    unsigned inc = 1u << ((b & 3u) * 8u);
    unsigned w = b >> 2;
    h[0] -= (w == 0) ? inc : 0u;
    h[1] -= (w == 1) ? inc : 0u;
    h[2] -= (w == 2) ? inc : 0u;
    h[3] -= (w == 3) ? inc : 0u;
    h[4] -= (w == 4) ? inc : 0u;
}

// first-max argmax over 17 byte counters (ascending bins => lowest bin wins ties)
__device__ __forceinline__ int argmax17(const unsigned h[5]) {
    unsigned m = __vmaxu4(__vmaxu4(h[0], h[1]), __vmaxu4(h[2], h[3]));
    m = __vmaxu4(m, h[4]);
    m = __vmaxu4(m, m >> 16);
    m = __vmaxu4(m, m >> 8);
    unsigned M = (m & 0xFFu) * 0x01010101u;
    unsigned e;
    e = __vcmpeq4(h[0], M); if (e) return (int)((__ffs(e) - 1) >> 3);
    e = __vcmpeq4(h[1], M); if (e) return 4  + (int)((__ffs(e) - 1) >> 3);
    e = __vcmpeq4(h[2], M); if (e) return 8  + (int)((__ffs(e) - 1) >> 3);
    e = __vcmpeq4(h[3], M); if (e) return 12 + (int)((__ffs(e) - 1) >> 3);
    return 16;
}

// quantize one float to bin (round-half-even, matching jnp: (x*255)/16 then rint)
__device__ __forceinline__ int qbin(float v) {
    int r = __float2int_rn(__fmul_rn(v, 255.0f) * 0.0625f);
    return max(0, min(16, r));
}

#define TY 8
#define TX 118
#define TXP 128          // input columns per tile (halo-padded)
#define TXS 132          // swizzle-padded scol width

__device__ __forceinline__ int pxi(int x) { return x + (x >> 5); }   // bank-swizzle index

__global__ __launch_bounds__(256) void k_mode(const float* __restrict__ x) {
    __shared__ unsigned char  sbin[2][18][TXP];     // 4608 B (ping-pong)
    __shared__ unsigned int   scol[5][TY][TXS];     // 21120 B, swizzled x-index
    __shared__ unsigned int   shist[NH];            // 9828 B (u16-packed)

    int tid = threadIdx.x;
    int b   = blockIdx.z;
    int OY0 = blockIdx.y * TY;
    int OX0 = blockIdx.x * TX;
    int TXv = min(TX, OHW - OX0);                   // valid output cols this tile
    bool interior = (OY0 >= 1) && (OY0 + 17 <= 512) && (OX0 >= 1) && (OX0 + 127 <= 512);

    for (int i = tid; i < NH; i += 256) shist[i] = 0u;

    const float* base = x + (size_t)b * 3 * 512 * 512;

    int yy = tid >> 5;
    int lane = tid & 31;
    int x0 = lane * 4;
    unsigned tl[4] = {0, 0, 0, 0};                  // register triple accumulators

    // ---- load + quantize channel c into sbin[c&1] (padding / out-of-tile -> bin 0)
    auto load_plane = [&](int c) {
        const float* plane = base + (size_t)c * 512 * 512;
        unsigned char (*sb)[TXP] = sbin[c & 1];
        if (interior) {
            const float* p = plane + (size_t)(OY0 - 1) * 512 + (OX0 - 1);
            #pragma unroll
            for (int k = 0; k < 9; k++) {           // 9*256 == 18*128 exactly
                int i = tid + k * 256;
                int iy = i >> 7, jx = i & 127;
                sb[iy][jx] = (unsigned char)qbin(p[iy * 512 + jx]);
            }
        } else {
            #pragma unroll
            for (int k = 0; k < 9; k++) {
                int i = tid + k * 256;
                int iy = i >> 7, jx = i & 127;
                int gy = OY0 - 1 + iy, gx = OX0 - 1 + jx;
                float v = -1.0f;                    // qbin(-1) -> 0 (pad)
                if (gy >= 0 && gy < 512 && gx >= 0 && gx < 512) v = plane[gy * 512 + gx];
                sb[iy][jx] = (unsigned char)qbin(v);
            }
        }
    };

    load_plane(0);
    __syncthreads();

    for (int c = 0; c < 3; c++) {
        const unsigned char (*sb)[TXP] = sbin[c & 1];
        // ---- column histograms, y-sliding: 128 columns x 2 half-strips = 256 tasks
        {
            int jx = tid & 127;
            int y0 = (tid >> 7) * 4;                 // 0 or 4
            int pj = pxi(jx);
            unsigned h[5] = {0, 0, 0, 0, 0};
            #pragma unroll
            for (int r = 0; r < 11; r++) padd(h, (unsigned)sb[y0 + r][jx]);
            #pragma unroll
            for (int w = 0; w < 5; w++) scol[w][y0][pj] = h[w];
            #pragma unroll
            for (int k = 1; k < 4; k++) {
                padd(h, (unsigned)sb[y0 + 10 + k][jx]);
                psub(h, (unsigned)sb[y0 + k - 1][jx]);
                #pragma unroll
                for (int w = 0; w < 5; w++) scol[w][y0 + k][pj] = h[w];
            }
        }
        // ---- issue next channel's loads into the OTHER sbin buffer
        if (c < 2) load_plane(c + 1);
        __syncthreads();   // orders scol for slide AND sbin[(c+1)&1] for next col
        // ---- sliding window in x, shuffle-assisted init:
        //      W(4l) = A(l) + A(l+1) + A(l+2) - C(4l+11),  A(l) = C(4l..4l+3)
        {
            unsigned A[5];
            #pragma unroll
            for (int w = 0; w < 5; w++) {
                A[w] = scol[w][yy][pxi(x0)]     + scol[w][yy][pxi(x0 + 1)]
                     + scol[w][yy][pxi(x0 + 2)] + scol[w][yy][pxi(x0 + 3)];
            }
            int xs = min(x0 + 11, TXP - 1);          // clamp for lanes 30/31 (unused)
            unsigned h[5];
            #pragma unroll
            for (int w = 0; w < 5; w++) {
                unsigned a1 = __shfl_down_sync(0xFFFFFFFFu, A[w], 1);
                unsigned a2 = __shfl_down_sync(0xFFFFFFFFu, A[w], 2);
                h[w] = A[w] + a1 + a2 - scol[w][yy][pxi(xs)];
            }
            if (x0 < TXv) {
                unsigned mul = (c == 0) ? 289u : (c == 1) ? 17u : 1u;
                int xe = min(x0 + 4, TXv);
                #pragma unroll
                for (int k = 0; k < 4; k++) {
                    int xx = x0 + k;
                    if (xx < xe) {
                        tl[k] += (unsigned)argmax17(h) * mul;
                        if (xx + 1 < xe) {
                            int pa = pxi(xx + 11), pb = pxi(xx);
                            #pragma unroll
                            for (int w = 0; w < 5; w++)
                                h[w] += scol[w][yy][pa] - scol[w][yy][pb];
                        }
                    }
                }
            }
        }
        __syncthreads();   // protects scol before next channel's column phase
    }
    // ---- write triples (packed u32 pairs, first pair always valid; tail guard on second)
    if (x0 < TXv) {
        int xe = min(x0 + 4, TXv);                   // 2 or 4 valid pixels (TXv even)
        size_t orow = ((size_t)b * OHW + OY0 + yy) * OHW + OX0 + x0;
        unsigned int* op = reinterpret_cast<unsigned int*>(&g_triple[orow]);
        op[0] = tl[0] | (tl[1] << 16);
        atomicAdd(&shist[tl[0] >> 1], 1u << ((tl[0] & 1u) * 16u));
        atomicAdd(&shist[tl[1] >> 1], 1u << ((tl[1] & 1u) * 16u));
        if (xe == x0 + 4) {
            op[1] = tl[2] | (tl[3] << 16);
            atomicAdd(&shist[tl[2] >> 1], 1u << ((tl[2] & 1u) * 16u));
            atomicAdd(&shist[tl[3] >> 1], 1u << ((tl[3] & 1u) * 16u));
        }
    }
    __syncthreads();
    for (int i = tid; i < NH; i += 256) {
        unsigned wv = shist[i];
        unsigned lo = wv & 0xFFFFu, hi = wv >> 16;
        if (lo) atomicAdd(&g_hist[2 * i], lo);
        if (hi) atomicAdd(&g_hist[2 * i + 1], hi);
    }
}

// ---------------------------------------------------------------- block reduce (2 doubles) + broadcast
__device__ __forceinline__ void reduce_bcast(double& s, double& s2, float* mean, float* rstd) {
    int tid = threadIdx.x, lane = tid & 31, wid = tid >> 5;
    #pragma unroll
    for (int off = 16; off; off >>= 1) {
        s  += __shfl_down_sync(0xFFFFFFFFu, s,  off);
        s2 += __shfl_down_sync(0xFFFFFFFFu, s2, off);
    }
    __shared__ double sh[8][2];
    __shared__ float  bc[2];
    if (lane == 0) { sh[wid][0] = s; sh[wid][1] = s2; }
    __syncthreads();
    if (tid == 0) {
        double ts = 0.0, tq = 0.0;
        #pragma unroll
        for (int w = 0; w < 8; w++) { ts += sh[w][0]; tq += sh[w][1]; }
        double mn = ts / (double)NPIX;
        double vr = tq / (double)NPIX - mn * mn;
        if (vr < 0.0) vr = 0.0;
        bc[0] = (float)mn;
        bc[1] = (float)(1.0 / sqrt(vr + 1e-5));
    }
    __syncthreads();
    *mean = bc[0]; *rstd = bc[1];
}

// ---------------------------------------------------------------- fused stage-1: BN stats + z1
__global__ __launch_bounds__(256) void kA(const float* __restrict__ w1, const float* __restrict__ b1,
                                          const float* __restrict__ wd1, const float* __restrict__ bd1,
                                          const float* __restrict__ g1, const float* __restrict__ be1) {
    int o = blockIdx.x, tid = threadIdx.x;
    float wa = w1[o * 3], wb = w1[o * 3 + 1], wc = w1[o * 3 + 2];
    float bb = b1[o], wdv = wd1[o], bdv = bd1[o];
    float gg = g1[o], bee = be1[o];
    float ys[20];
    double s = 0.0, s2 = 0.0;
    #pragma unroll
    for (int i = 0; i < 20; i++) {
        int t = tid + i * 256;
        if (t < NB) {
            int m0 = t / 289; int rem = t - m0 * 289; int m1 = rem / 17; int m2 = rem - m1 * 17;
            float y = (wa * (float)m0 + wb * (float)m1 + wc * (float)m2) * 0.0625f + bb;
            y = y * wdv + bdv;
            ys[i] = y;
            double n = (double)g_hist[t];
            s  += n * (double)y;
            s2 += n * (double)y * (double)y;
        }
    }
    float mean, rstd;
    reduce_bcast(s, s2, &mean, &rstd);
    #pragma unroll
    for (int i = 0; i < 20; i++) {
        int t = tid + i * 256;
        if (t < NB) {
            float z = (ys[i] - mean) * rstd * gg + bee;
            z = (z >= 0.f) ? z : 0.01f * z;
            g_z1T[o * NB + t] = z;
        }
    }
}

// ---------------------------------------------------------------- fused stage-2: BN stats + final LUT
__global__ __launch_bounds__(256) void kB(const float* __restrict__ w2, const float* __restrict__ b2,
                                          const float* __restrict__ wd2, const float* __restrict__ bd2,
                                          const float* __restrict__ g2, const float* __restrict__ be2) {
    int o = blockIdx.x, tid = threadIdx.x;
    __shared__ float wsh[CH];
    if (tid < CH) wsh[tid] = w2[o * CH + tid];
    __syncthreads();
    float bb = b2[o], wdv = wd2[o], bdv = bd2[o];
    float gg = g2[o], bee = be2[o];
    float ys[20];
    double s = 0.0, s2 = 0.0;
    #pragma unroll
    for (int i = 0; i < 20; i++) {
        int t = tid + i * 256;
        if (t < NB) {
            float acc = 0.f;
            #pragma unroll
            for (int c = 0; c < CH; c++) acc += wsh[c] * g_z1T[c * NB + t];
            float y = (acc + bb) * wdv + bdv;
            ys[i] = y;
            double n = (double)g_hist[t];
            s  += n * (double)y;
            s2 += n * (double)y * (double)y;
        }
    }
    float mean, rstd;
    reduce_bcast(s, s2, &mean, &rstd);
    #pragma unroll
    for (int i = 0; i < 20; i++) {
        int t = tid + i * 256;
        if (t < NB) {
            float z = (ys[i] - mean) * rstd * gg + bee;
            z = (z >= 0.f) ? z : 0.01f * z;
            g_lut[t * CH + o] = z;
        }
    }
}

// ---------------------------------------------------------------- expand to [8,32,504,504]
// 8-lanes-per-pixel gather (each LDG.128 touches only 4 cache lines -> half the
// L1 wavefronts of the 4-lane layout). Even stride 66 keeps float2 reads 8B-
// aligned; a 1-bit XOR column swizzle (flip bit2 for channels >= 16) makes both
// the STS and LDS.64 phases bank-conflict-free. Split prefetch + streaming stores.
#define EXP_PX 64            // pixels per pass (PLANE % 64 == 0)
#define EXP_PASS 16          // passes per block => 1024 px/block
__global__ __launch_bounds__(256) void k_expand(float* __restrict__ out) {
    __shared__ float sm[2][CH][66];   // 16896 B
    int tid  = threadIdx.x;
    int w    = tid >> 5, lane = tid & 31;
    int b    = blockIdx.y;
    int r0   = blockIdx.x * (EXP_PX * EXP_PASS);

    // re-zero g_hist for the next graph replay (k_expand never reads it)
    if (b == 0 && blockIdx.x < 20) {
        int i = blockIdx.x * 256 + tid;
        if (i < NB) g_hist[i] = 0u;
    }

    const unsigned short* trip = g_triple + (size_t)b * PLANE;
    float* ob = out + (size_t)b * CH * PLANE;

    int c   = lane & 7;             // float4 chunk within LUT row (channels 4c..4c+3)
    int ch0 = 4 * c;
    int sw  = c & 4;                // column XOR swizzle: 4 iff channel >= 16
    int pl0 = w * 8 + (lane >> 3);  // first pixel (0..63), second = pl0 + 4
    int pl1 = pl0 + 4;
    int ca  = pl0 ^ sw, cb = pl1 ^ sw;   // swizzled columns for this thread's chunk
    int npass = min(EXP_PASS, (PLANE - r0) / EXP_PX);

    // prologue: gather pass 0 (two pixels per thread), prefetch triples for pass 1
    unsigned t0a = (unsigned)trip[r0 + pl0];
    unsigned t0b = (unsigned)trip[r0 + pl1];
    float4 v0 = reinterpret_cast<const float4*>(g_lut + (size_t)t0a * CH)[c];
    float4 v1 = reinterpret_cast<const float4*>(g_lut + (size_t)t0b * CH)[c];
    unsigned tna = 0u, tnb = 0u;
    if (npass > 1) {
        tna = (unsigned)trip[r0 + EXP_PX + pl0];
        tnb = (unsigned)trip[r0 + EXP_PX + pl1];
    }

    for (int pass = 0; pass < npass; pass++) {
        int p0  = r0 + pass * EXP_PX;
        int buf = pass & 1;
        sm[buf][ch0 + 0][ca] = v0.x;   sm[buf][ch0 + 0][cb] = v1.x;
        sm[buf][ch0 + 1][ca] = v0.y;   sm[buf][ch0 + 1][cb] = v1.y;
        sm[buf][ch0 + 2][ca] = v0.z;   sm[buf][ch0 + 2][cb] = v1.z;
        sm[buf][ch0 + 3][ca] = v0.w;   sm[buf][ch0 + 3][cb] = v1.w;
        // prefetch chain (before barrier; overlaps the store phase)
        if (pass + 1 < npass) {
            v0 = reinterpret_cast<const float4*>(g_lut + (size_t)tna * CH)[c];
            v1 = reinterpret_cast<const float4*>(g_lut + (size_t)tnb * CH)[c];
        }
        if (pass + 2 < npass) {
            tna = (unsigned)trip[p0 + 2 * EXP_PX + pl0];
            tnb = (unsigned)trip[p0 + 2 * EXP_PX + pl1];
        }
        __syncthreads();
        #pragma unroll
        for (int k = 0; k < 4; k++) {
            int ch = w * 4 + k;
            int cs = (ch & 16) >> 2;   // same swizzle on the read side
            float2 v = *reinterpret_cast<const float2*>(&sm[buf][ch][(lane * 2) ^ cs]);
            __stcs(reinterpret_cast<float2*>(&ob[(size_t)ch * PLANE + p0 + lane * 2]), v);
        }
    }
}

// ---------------------------------------------------------------- launch
extern "C" void kernel_launch(void* const* d_in, const int* in_sizes, int n_in,
                              void* d_out, int out_size) {
    const float* x   = (const float*)d_in[0];
    const float* w1  = (const float*)d_in[1];
    const float* b1  = (const float*)d_in[2];
    const float* wd1 = (const float*)d_in[3];
    const float* bd1 = (const float*)d_in[4];
    const float* g1  = (const float*)d_in[5];
    const float* be1 = (const float*)d_in[6];
    const float* w2  = (const float*)d_in[7];
    const float* b2  = (const float*)d_in[8];
    const float* wd2 = (const float*)d_in[9];
    const float* bd2 = (const float*)d_in[10];
    const float* g2  = (const float*)d_in[11];
    const float* be2 = (const float*)d_in[12];
    float* out = (float*)d_out;

    k_mode<<<dim3((OHW + TX - 1) / TX, OHW / TY, B_), 256>>>(x);   // (5,63,8)
    kA<<<CH, 256>>>(w1, b1, wd1, bd1, g1, be1);
    kB<<<CH, 256>>>(w2, b2, wd2, bd2, g2, be2);
    int xblocks = (PLANE + EXP_PX * EXP_PASS - 1) / (EXP_PX * EXP_PASS);  // 249
    k_expand<<<dim3(xblocks, B_), 256>>>(out);
}